// round 14
// baseline (speedup 1.0000x reference)
#include <cuda_runtime.h>
#include <cuda_fp16.h>
#include <cuda_bf16.h>
#include <cstdint>
#include <cstddef>

#define N_NODES 50000
#define E_EDGES 800000
#define D 128

// Scratch (device globals -- no allocation allowed)
__device__ float   g_deg[N_NODES];
__device__ float   g_dinv[N_NODES];
__device__ __half2 g_yh[(size_t)N_NODES * 64];   // y = dinv*xlin, fp16 packed
__device__ __half  g_Whi[D * D];
__device__ __half  g_Wlo[D * D];

// ---------------------------------------------------------------------------
// Fused setup: W split (i < D*D) + deg init to 1 (self-loop) for i < N.
__global__ void k_setup(const float* __restrict__ W) {
    int i = blockIdx.x * blockDim.x + threadIdx.x;
    if (i < D * D) {
        float v   = W[i];
        __half hi = __float2half_rn(v);
        __half lo = __float2half_rn(v - __half2float(hi));
        g_Whi[i] = hi;
        g_Wlo[i] = lo;
    }
    if (i < N_NODES) g_deg[i] = 1.0f;
}

__global__ void k_count(const int* __restrict__ dst) {
    int e = blockIdx.x * blockDim.x + threadIdx.x;
    if (e < E_EDGES) atomicAdd(&g_deg[dst[e]], 1.0f);
}

__global__ void k_dinv() {
    int i = blockIdx.x * blockDim.x + threadIdx.x;
    if (i < N_NODES) g_dinv[i] = rsqrtf(g_deg[i]);
}

// ---------------------------------------------------------------------------
// Tensor-core GEMM, fp16 2-term split (Markidis).
// BM=64 rows/CTA, 256 threads = 8 warps: wm = wid&3 (m-tile), wn = wid>>2.
// A-fragments loaded DIRECTLY from global x (float2 per lane), converted
// in-register to hi/lo. Only W lives in smem (68KB) -> 2 CTAs/SM, no inner
// __syncthreads().

#define W_STRIDE 136
#define WS_ARR (128 * W_STRIDE)            // halves
#define GEMM_SMEM_BYTES (2 * WS_ARR * 2)   // 69632 B

struct Frag4 { uint32_t r[4]; };

__device__ __forceinline__ void ldsm4(Frag4& f, uint32_t addr) {
    asm volatile(
        "ldmatrix.sync.aligned.m8n8.x4.shared.b16 {%0,%1,%2,%3}, [%4];"
        : "=r"(f.r[0]), "=r"(f.r[1]), "=r"(f.r[2]), "=r"(f.r[3])
        : "r"(addr));
}

__device__ __forceinline__ void mma16816(float* c, const Frag4& a,
                                         uint32_t b0, uint32_t b1) {
    asm volatile(
        "mma.sync.aligned.m16n8k16.row.col.f32.f16.f16.f32 "
        "{%0,%1,%2,%3}, {%4,%5,%6,%7}, {%8,%9}, {%0,%1,%2,%3};"
        : "+f"(c[0]), "+f"(c[1]), "+f"(c[2]), "+f"(c[3])
        : "r"(a.r[0]), "r"(a.r[1]), "r"(a.r[2]), "r"(a.r[3]),
          "r"(b0), "r"(b1));
}

__device__ __forceinline__ uint32_t hi_bits(float a, float b) {
    __half2 h = __halves2half2(__float2half_rn(a), __float2half_rn(b));
    return *(uint32_t*)&h;
}

__device__ __forceinline__ uint32_t lo_bits(float a, float b) {
    float ra = a - __half2float(__float2half_rn(a));
    float rb = b - __half2float(__float2half_rn(b));
    __half2 h = __halves2half2(__float2half_rn(ra), __float2half_rn(rb));
    return *(uint32_t*)&h;
}

__global__ __launch_bounds__(256, 2)
void k_gemm_mma(const float* __restrict__ x, const float* __restrict__ b,
                float* __restrict__ out) {
    extern __shared__ __half sm[];
    __half* Ws_hi = sm;
    __half* Ws_lo = sm + WS_ARR;

    const int tid  = threadIdx.x;
    const int lane = tid & 31;
    const int wid  = tid >> 5;        // 0..7
    const int wm   = wid & 3;         // m-tile -> rows wm*16..+15
    const int wn   = wid >> 2;        // n-half (0/1)
    const int m0   = blockIdx.x * 64;

    // ---- Stage W (128x128 hi/lo): vector copies from precomputed split ----
    for (int i = tid; i < 128 * 16; i += 256) {
        int r = i >> 4;
        int c = i & 15;              // uint4 index (8 halves each)
        *(uint4*)(Ws_hi + r * W_STRIDE + c * 8) =
            *(const uint4*)(g_Whi + r * 128 + c * 8);
        *(uint4*)(Ws_lo + r * W_STRIDE + c * 8) =
            *(const uint4*)(g_Wlo + r * 128 + c * 8);
    }
    __syncthreads();

    // A addressing: quad-pair layout of m16n8k16
    const int gid  = lane >> 2;       // 0..7
    const int tig  = lane & 3;        // 0..3
    const int row0 = m0 + wm * 16 + gid;
    const int row1 = row0 + 8;
    const bool v0  = (row0 < N_NODES);
    const bool v1  = (row1 < N_NODES);
    const float* xr0 = x + (size_t)(v0 ? row0 : 0) * D;
    const float* xr1 = x + (size_t)(v1 ? row1 : 0) * D;

    // B ldsm addressing
    const int bRow = ((lane >> 4) & 1) * 8 + (lane & 7);
    const int bCol = ((lane >> 3) & 1) * 8;
    const uint32_t ws_hi_b = (uint32_t)__cvta_generic_to_shared(Ws_hi);
    const uint32_t ws_lo_b = (uint32_t)__cvta_generic_to_shared(Ws_lo);

    float acc[8][4];
#pragma unroll
    for (int n = 0; n < 8; n++) {
#pragma unroll
        for (int j = 0; j < 4; j++) acc[n][j] = 0.0f;
    }

    const float2 fz = make_float2(0.f, 0.f);
    // Software pipeline: preload A floats for ks=0
    float2 f00, f10, f01, f11;
    {
        const int c0 = 2 * tig;
        f00 = v0 ? *(const float2*)(xr0 + c0)     : fz;
        f10 = v1 ? *(const float2*)(xr1 + c0)     : fz;
        f01 = v0 ? *(const float2*)(xr0 + c0 + 8) : fz;
        f11 = v1 ? *(const float2*)(xr1 + c0 + 8) : fz;
    }

#pragma unroll
    for (int ks = 0; ks < 8; ks++) {
        // Prefetch next K-step's A floats
        float2 n00 = fz, n10 = fz, n01 = fz, n11 = fz;
        if (ks < 7) {
            const int c0 = (ks + 1) * 16 + 2 * tig;
            n00 = v0 ? *(const float2*)(xr0 + c0)     : fz;
            n10 = v1 ? *(const float2*)(xr1 + c0)     : fz;
            n01 = v0 ? *(const float2*)(xr0 + c0 + 8) : fz;
            n11 = v1 ? *(const float2*)(xr1 + c0 + 8) : fz;
        }

        // Convert current A to hi/lo fragments
        Frag4 ah, al;
        ah.r[0] = hi_bits(f00.x, f00.y);
        ah.r[1] = hi_bits(f10.x, f10.y);
        ah.r[2] = hi_bits(f01.x, f01.y);
        ah.r[3] = hi_bits(f11.x, f11.y);
        al.r[0] = lo_bits(f00.x, f00.y);
        al.r[1] = lo_bits(f10.x, f10.y);
        al.r[2] = lo_bits(f01.x, f01.y);
        al.r[3] = lo_bits(f11.x, f11.y);

        // Load ALL B fragments for this K-step (8 ldsm), then 24 MMAs with
        // 8 independent accumulator chains.
        const int kg = ks * 16;
        Frag4 bh[4], bl[4];
#pragma unroll
        for (int pl = 0; pl < 4; pl++) {
            const int p = wn * 4 + pl;
            const uint32_t boff =
                (uint32_t)((p * 16 + bRow) * W_STRIDE + kg + bCol) * 2;
            ldsm4(bh[pl], ws_hi_b + boff);
            ldsm4(bl[pl], ws_lo_b + boff);
        }

#pragma unroll
        for (int pl = 0; pl < 4; pl++) {
            mma16816(acc[2 * pl],     ah, bh[pl].r[0], bh[pl].r[1]);
            mma16816(acc[2 * pl + 1], ah, bh[pl].r[2], bh[pl].r[3]);
        }
#pragma unroll
        for (int pl = 0; pl < 4; pl++) {
            mma16816(acc[2 * pl],     ah, bl[pl].r[0], bl[pl].r[1]);
            mma16816(acc[2 * pl + 1], ah, bl[pl].r[2], bl[pl].r[3]);
        }
#pragma unroll
        for (int pl = 0; pl < 4; pl++) {
            mma16816(acc[2 * pl],     al, bh[pl].r[0], bh[pl].r[1]);
            mma16816(acc[2 * pl + 1], al, bh[pl].r[2], bh[pl].r[3]);
        }

        f00 = n00; f10 = n10; f01 = n01; f11 = n11;
    }

    // Epilogue: g_yh = fp16(dinv*xlin) ; out = dinv^2*xlin + b
    float di0 = v0 ? g_dinv[row0] : 0.0f;
    float di1 = v1 ? g_dinv[row1] : 0.0f;

#pragma unroll
    for (int ntl = 0; ntl < 8; ntl++) {
        int nt = wn * 8 + ntl;
        int n  = nt * 8 + tig * 2;
        float b0 = b[n];
        float b1 = b[n + 1];
        if (v0) {
            float y0 = acc[ntl][0] * di0;
            float y1 = acc[ntl][1] * di0;
            g_yh[(size_t)row0 * 64 + nt * 4 + tig] = __floats2half2_rn(y0, y1);
            float2 o;
            o.x = y0 * di0 + b0;
            o.y = y1 * di0 + b1;
            *(float2*)(out + (size_t)row0 * D + n) = o;
        }
        if (v1) {
            float y0 = acc[ntl][2] * di1;
            float y1 = acc[ntl][3] * di1;
            g_yh[(size_t)row1 * 64 + nt * 4 + tig] = __floats2half2_rn(y0, y1);
            float2 o;
            o.x = y0 * di1 + b0;
            o.y = y1 * di1 + b1;
            *(float2*)(out + (size_t)row1 * D + n) = o;
        }
    }
}

// ---------------------------------------------------------------------------
// Edge scatter: one warp per edge; lane handles 4 floats (2 half2 = 8B gather).
// y pre-scaled by dinv[src]; msg = dinv[dst] * y[src]. Accumulate fp32.
__global__ __launch_bounds__(256)
void k_edges(const int* __restrict__ src, const int* __restrict__ dst,
             float* __restrict__ out) {
    int w    = (blockIdx.x * blockDim.x + threadIdx.x) >> 5;
    int lane = threadIdx.x & 31;
    if (w >= E_EDGES) return;

    int s = __ldg(src + w);
    int d = __ldg(dst + w);
    float nd = g_dinv[d];

    const __half2* yp = g_yh + (size_t)s * 64 + lane * 2;
    uint2 raw = *(const uint2*)yp;
    __half2 h0 = *(const __half2*)&raw.x;
    __half2 h1 = *(const __half2*)&raw.y;
    float2 f0 = __half22float2(h0);
    float2 f1 = __half22float2(h1);

    float* p = out + (size_t)d * D + lane * 4;
    asm volatile("red.global.add.v4.f32 [%0], {%1, %2, %3, %4};" ::
                 "l"(p),
                 "f"(f0.x * nd), "f"(f0.y * nd),
                 "f"(f1.x * nd), "f"(f1.y * nd)
                 : "memory");
}

// ---------------------------------------------------------------------------
extern "C" void kernel_launch(void* const* d_in, const int* in_sizes, int n_in,
                              void* d_out, int out_size) {
    const float* x  = (const float*)d_in[0];
    const int*   ei = (const int*)d_in[1];   // [2, E]: row 0 = src, row 1 = dst
    const float* W  = (const float*)d_in[2];
    const float* b  = (const float*)d_in[3];
    float* out = (float*)d_out;

    const int* src = ei;
    const int* dst = ei + E_EDGES;

    cudaFuncSetAttribute(k_gemm_mma,
                         cudaFuncAttributeMaxDynamicSharedMemorySize,
                         GEMM_SMEM_BYTES);

    k_setup<<<(N_NODES + 255) / 256, 256>>>(W);
    k_count<<<(E_EDGES + 255) / 256, 256>>>(dst);
    k_dinv<<<(N_NODES + 255) / 256, 256>>>();
    k_gemm_mma<<<(N_NODES + 63) / 64, 256, GEMM_SMEM_BYTES>>>(x, b, out);

    long long total = (long long)E_EDGES * 32;
    int blocks = (int)((total + 255) / 256);
    k_edges<<<blocks, 256>>>(src, dst, out);
}

// round 17
// speedup vs baseline: 1.0358x; 1.0358x over previous
#include <cuda_runtime.h>
#include <cuda_fp16.h>
#include <cuda_bf16.h>
#include <cstdint>
#include <cstddef>

#define N_NODES 50000
#define E_EDGES 800000
#define D 128

// Scratch (device globals -- no allocation allowed).
// g_deg is zero-initialized at module load; k_dinv resets it to zero after
// each use so every graph replay sees the same initial state.
__device__ float   g_deg[N_NODES];
__device__ float   g_dinv[N_NODES];
__device__ __half2 g_yh[(size_t)N_NODES * 64];   // y = dinv*xlin, fp16 packed
__device__ __half  g_Whi[D * D];
__device__ __half  g_Wlo[D * D];

// ---------------------------------------------------------------------------
// Fused: degree histogram over dst (+1 handled later) and W hi/lo split.
__global__ void k_count_prep(const int* __restrict__ dst,
                             const float* __restrict__ W) {
    int i = blockIdx.x * blockDim.x + threadIdx.x;
    if (i < D * D) {
        float v   = W[i];
        __half hi = __float2half_rn(v);
        __half lo = __float2half_rn(v - __half2float(hi));
        g_Whi[i] = hi;
        g_Wlo[i] = lo;
    }
    if (i < E_EDGES) atomicAdd(&g_deg[dst[i]], 1.0f);
}

// dinv = rsqrt(deg + 1)  (the +1 is the self-loop); reset deg for next replay.
__global__ void k_dinv() {
    int i = blockIdx.x * blockDim.x + threadIdx.x;
    if (i < N_NODES) {
        float dg = g_deg[i];
        g_dinv[i] = rsqrtf(dg + 1.0f);
        g_deg[i] = 0.0f;
    }
}

// ---------------------------------------------------------------------------
// Tensor-core GEMM, fp16 2-term split (Markidis).
// BM=64 rows/CTA, 256 threads = 8 warps: wm = wid&3 (m-tile), wn = wid>>2.
// A-fragments loaded directly from global x (float2 per lane), converted
// in-register to hi/lo. Only W in smem (68KB).

#define W_STRIDE 136
#define WS_ARR (128 * W_STRIDE)            // halves
#define GEMM_SMEM_BYTES (2 * WS_ARR * 2)   // 69632 B

struct Frag4 { uint32_t r[4]; };

__device__ __forceinline__ void ldsm4(Frag4& f, uint32_t addr) {
    asm volatile(
        "ldmatrix.sync.aligned.m8n8.x4.shared.b16 {%0,%1,%2,%3}, [%4];"
        : "=r"(f.r[0]), "=r"(f.r[1]), "=r"(f.r[2]), "=r"(f.r[3])
        : "r"(addr));
}

__device__ __forceinline__ void mma16816(float* c, const Frag4& a,
                                         uint32_t b0, uint32_t b1) {
    asm volatile(
        "mma.sync.aligned.m16n8k16.row.col.f32.f16.f16.f32 "
        "{%0,%1,%2,%3}, {%4,%5,%6,%7}, {%8,%9}, {%0,%1,%2,%3};"
        : "+f"(c[0]), "+f"(c[1]), "+f"(c[2]), "+f"(c[3])
        : "r"(a.r[0]), "r"(a.r[1]), "r"(a.r[2]), "r"(a.r[3]),
          "r"(b0), "r"(b1));
}

__device__ __forceinline__ uint32_t hi_bits(float a, float b) {
    __half2 h = __halves2half2(__float2half_rn(a), __float2half_rn(b));
    return *(uint32_t*)&h;
}

__device__ __forceinline__ uint32_t lo_bits(float a, float b) {
    float ra = a - __half2float(__float2half_rn(a));
    float rb = b - __half2float(__float2half_rn(b));
    __half2 h = __halves2half2(__float2half_rn(ra), __float2half_rn(rb));
    return *(uint32_t*)&h;
}

__global__ __launch_bounds__(256)
void k_gemm_mma(const float* __restrict__ x, const float* __restrict__ b,
                float* __restrict__ out) {
    extern __shared__ __half sm[];
    __half* Ws_hi = sm;
    __half* Ws_lo = sm + WS_ARR;

    const int tid  = threadIdx.x;
    const int lane = tid & 31;
    const int wid  = tid >> 5;        // 0..7
    const int wm   = wid & 3;         // m-tile -> rows wm*16..+15
    const int wn   = wid >> 2;        // n-half (0/1)
    const int m0   = blockIdx.x * 64;

    // ---- Stage W (128x128 hi/lo): vector copies from precomputed split ----
    for (int i = tid; i < 128 * 16; i += 256) {
        int r = i >> 4;
        int c = i & 15;              // uint4 index (8 halves each)
        *(uint4*)(Ws_hi + r * W_STRIDE + c * 8) =
            *(const uint4*)(g_Whi + r * 128 + c * 8);
        *(uint4*)(Ws_lo + r * W_STRIDE + c * 8) =
            *(const uint4*)(g_Wlo + r * 128 + c * 8);
    }
    __syncthreads();

    // A addressing: quad-pair layout of m16n8k16
    const int gid  = lane >> 2;       // 0..7
    const int tig  = lane & 3;        // 0..3
    const int row0 = m0 + wm * 16 + gid;
    const int row1 = row0 + 8;
    const bool v0  = (row0 < N_NODES);
    const bool v1  = (row1 < N_NODES);
    const float* xr0 = x + (size_t)(v0 ? row0 : 0) * D;
    const float* xr1 = x + (size_t)(v1 ? row1 : 0) * D;

    // B ldsm addressing
    const int bRow = ((lane >> 4) & 1) * 8 + (lane & 7);
    const int bCol = ((lane >> 3) & 1) * 8;
    const uint32_t ws_hi_b = (uint32_t)__cvta_generic_to_shared(Ws_hi);
    const uint32_t ws_lo_b = (uint32_t)__cvta_generic_to_shared(Ws_lo);

    float acc[8][4];
#pragma unroll
    for (int n = 0; n < 8; n++) {
#pragma unroll
        for (int j = 0; j < 4; j++) acc[n][j] = 0.0f;
    }

    const float2 fz = make_float2(0.f, 0.f);

#pragma unroll
    for (int ks = 0; ks < 8; ks++) {
        // Load current K-step's A floats (L2-resident)
        const int c0 = ks * 16 + 2 * tig;
        float2 f00 = v0 ? *(const float2*)(xr0 + c0)     : fz;
        float2 f10 = v1 ? *(const float2*)(xr1 + c0)     : fz;
        float2 f01 = v0 ? *(const float2*)(xr0 + c0 + 8) : fz;
        float2 f11 = v1 ? *(const float2*)(xr1 + c0 + 8) : fz;

        // Convert to hi/lo fragments
        Frag4 ah, al;
        ah.r[0] = hi_bits(f00.x, f00.y);
        ah.r[1] = hi_bits(f10.x, f10.y);
        ah.r[2] = hi_bits(f01.x, f01.y);
        ah.r[3] = hi_bits(f11.x, f11.y);
        al.r[0] = lo_bits(f00.x, f00.y);
        al.r[1] = lo_bits(f10.x, f10.y);
        al.r[2] = lo_bits(f01.x, f01.y);
        al.r[3] = lo_bits(f11.x, f11.y);

        // Load all B fragments for this K-step (8 ldsm), then 24 MMAs on
        // 8 independent accumulator chains.
        const int kg = ks * 16;
        Frag4 bh[4], bl[4];
#pragma unroll
        for (int pl = 0; pl < 4; pl++) {
            const int p = wn * 4 + pl;
            const uint32_t boff =
                (uint32_t)((p * 16 + bRow) * W_STRIDE + kg + bCol) * 2;
            ldsm4(bh[pl], ws_hi_b + boff);
            ldsm4(bl[pl], ws_lo_b + boff);
        }

#pragma unroll
        for (int pl = 0; pl < 4; pl++) {
            mma16816(acc[2 * pl],     ah, bh[pl].r[0], bh[pl].r[1]);
            mma16816(acc[2 * pl + 1], ah, bh[pl].r[2], bh[pl].r[3]);
        }
#pragma unroll
        for (int pl = 0; pl < 4; pl++) {
            mma16816(acc[2 * pl],     ah, bl[pl].r[0], bl[pl].r[1]);
            mma16816(acc[2 * pl + 1], ah, bl[pl].r[2], bl[pl].r[3]);
        }
#pragma unroll
        for (int pl = 0; pl < 4; pl++) {
            mma16816(acc[2 * pl],     al, bh[pl].r[0], bh[pl].r[1]);
            mma16816(acc[2 * pl + 1], al, bh[pl].r[2], bh[pl].r[3]);
        }
    }

    // Epilogue: g_yh = fp16(dinv*xlin) ; out = dinv^2*xlin + b
    float di0 = v0 ? g_dinv[row0] : 0.0f;
    float di1 = v1 ? g_dinv[row1] : 0.0f;

#pragma unroll
    for (int ntl = 0; ntl < 8; ntl++) {
        int nt = wn * 8 + ntl;
        int n  = nt * 8 + tig * 2;
        float b0 = b[n];
        float b1 = b[n + 1];
        if (v0) {
            float y0 = acc[ntl][0] * di0;
            float y1 = acc[ntl][1] * di0;
            g_yh[(size_t)row0 * 64 + nt * 4 + tig] = __floats2half2_rn(y0, y1);
            float2 o;
            o.x = y0 * di0 + b0;
            o.y = y1 * di0 + b1;
            *(float2*)(out + (size_t)row0 * D + n) = o;
        }
        if (v1) {
            float y0 = acc[ntl][2] * di1;
            float y1 = acc[ntl][3] * di1;
            g_yh[(size_t)row1 * 64 + nt * 4 + tig] = __floats2half2_rn(y0, y1);
            float2 o;
            o.x = y0 * di1 + b0;
            o.y = y1 * di1 + b1;
            *(float2*)(out + (size_t)row1 * D + n) = o;
        }
    }
}

// ---------------------------------------------------------------------------
// Edge scatter: one warp per edge; lane handles 4 floats (2 half2 = 8B gather).
// y pre-scaled by dinv[src]; msg = dinv[dst] * y[src]. Accumulate fp32.
__global__ __launch_bounds__(256)
void k_edges(const int* __restrict__ src, const int* __restrict__ dst,
             float* __restrict__ out) {
    int w    = (blockIdx.x * blockDim.x + threadIdx.x) >> 5;
    int lane = threadIdx.x & 31;
    if (w >= E_EDGES) return;

    int s = __ldg(src + w);
    int d = __ldg(dst + w);
    float nd = g_dinv[d];

    const __half2* yp = g_yh + (size_t)s * 64 + lane * 2;
    uint2 raw = *(const uint2*)yp;
    __half2 h0 = *(const __half2*)&raw.x;
    __half2 h1 = *(const __half2*)&raw.y;
    float2 f0 = __half22float2(h0);
    float2 f1 = __half22float2(h1);

    float* p = out + (size_t)d * D + lane * 4;
    asm volatile("red.global.add.v4.f32 [%0], {%1, %2, %3, %4};" ::
                 "l"(p),
                 "f"(f0.x * nd), "f"(f0.y * nd),
                 "f"(f1.x * nd), "f"(f1.y * nd)
                 : "memory");
}

// ---------------------------------------------------------------------------
extern "C" void kernel_launch(void* const* d_in, const int* in_sizes, int n_in,
                              void* d_out, int out_size) {
    const float* x  = (const float*)d_in[0];
    const int*   ei = (const int*)d_in[1];   // [2, E]: row 0 = src, row 1 = dst
    const float* W  = (const float*)d_in[2];
    const float* b  = (const float*)d_in[3];
    float* out = (float*)d_out;

    const int* src = ei;
    const int* dst = ei + E_EDGES;

    cudaFuncSetAttribute(k_gemm_mma,
                         cudaFuncAttributeMaxDynamicSharedMemorySize,
                         GEMM_SMEM_BYTES);

    k_count_prep<<<(E_EDGES + 255) / 256, 256>>>(dst, W);
    k_dinv<<<(N_NODES + 255) / 256, 256>>>();
    k_gemm_mma<<<(N_NODES + 63) / 64, 256, GEMM_SMEM_BYTES>>>(x, b, out);

    long long total = (long long)E_EDGES * 32;
    int blocks = (int)((total + 255) / 256);
    k_edges<<<blocks, 256>>>(src, dst, out);
}